// round 12
// baseline (speedup 1.0000x reference)
#include <cuda_runtime.h>
#include <cuda_fp16.h>
#include <stdint.h>

#define Bsz 8
#define H   12
#define Nq  1024
#define Dh  64
#define SCALE 0.125f
#define EPS 1e-6f

#define BM 64
#define BN 64
#define NT 128
#define NTILES (Nq / BN)   // 16
#define RPITCH 144          // bytes per smem row (72 halves: 64 data + 8 pad)

// smem byte offsets (per CTA: 46080 B -> 4 CTAs/SM)
#define SM_Q  0         // 64 rows -> 9216 B
#define SM_K0 9216
#define SM_K1 18432
#define SM_V0 27648
#define SM_V1 36864
#define SMEM_BYTES 46080

__device__ __forceinline__ uint32_t s2u(const void* p) {
    uint32_t a;
    asm("{ .reg .u64 t; cvta.to.shared.u64 t, %1; cvt.u32.u64 %0, t; }" : "=r"(a) : "l"(p));
    return a;
}
__device__ __forceinline__ uint32_t ph2(float lo, float hi) {
    __half2 h = __floats2half2_rn(lo, hi);
    return *(uint32_t*)&h;
}
__device__ __forceinline__ void ldm_x4(uint32_t r[4], uint32_t addr) {
    asm volatile("ldmatrix.sync.aligned.m8n8.x4.shared.b16 {%0,%1,%2,%3}, [%4];"
                 : "=r"(r[0]), "=r"(r[1]), "=r"(r[2]), "=r"(r[3]) : "r"(addr));
}
__device__ __forceinline__ void ldm_x4t(uint32_t r[4], uint32_t addr) {
    asm volatile("ldmatrix.sync.aligned.m8n8.x4.trans.shared.b16 {%0,%1,%2,%3}, [%4];"
                 : "=r"(r[0]), "=r"(r[1]), "=r"(r[2]), "=r"(r[3]) : "r"(addr));
}
__device__ __forceinline__ void mma16(float c[4], const uint32_t a[4],
                                      uint32_t b0, uint32_t b1) {
    asm volatile(
        "mma.sync.aligned.m16n8k16.row.col.f32.f16.f16.f32 "
        "{%0,%1,%2,%3},{%4,%5,%6,%7},{%8,%9},{%0,%1,%2,%3};\n"
        : "+f"(c[0]), "+f"(c[1]), "+f"(c[2]), "+f"(c[3])
        : "r"(a[0]), "r"(a[1]), "r"(a[2]), "r"(a[3]), "r"(b0), "r"(b1));
}

__global__ __launch_bounds__(NT, 4) void l2q_h7_kernel(
    const float* __restrict__ q, const float* __restrict__ k,
    const float* __restrict__ v, const float* __restrict__ alpha,
    const float* __restrict__ beta, const float* __restrict__ gamma,
    float* __restrict__ out)
{
    extern __shared__ char smc[];
    const uint32_t sb = s2u(smc);

    const int tid  = threadIdx.x;
    const int w    = tid >> 5;    // warp 0..3 -> rows w*16..w*16+15
    const int lane = tid & 31;
    const int g    = lane >> 2;
    const int t    = lane & 3;

    const int bh = blockIdx.y;
    const int h  = bh % H;
    const int m0 = blockIdx.x * BM;

    const float* qb = q + (size_t)bh * Nq * Dh;
    const float* kb = k + (size_t)bh * Nq * Dh;
    const float* vb = v + (size_t)bh * Nq * Dh;
    float*       ob = out + (size_t)bh * Nq * Dh;

    const float a2c = alpha[h] * SCALE * SCALE;
    const float b1c = beta[h] * SCALE;
    const float g0c = gamma[h];

    // ldmatrix lane-address offsets (verified layouts, rounds 4-11)
    const uint32_t qaddr = sb + SM_Q + (uint32_t)(w * 16 + (lane & 15)) * RPITCH
                         + (uint32_t)((lane >> 4) << 4);
    const uint32_t krow_off = (uint32_t)((lane & 7) + ((lane >> 4) << 3)) * RPITCH
                            + (uint32_t)(((lane >> 3) & 1) << 4);
    const uint32_t vrow_off = (uint32_t)((lane & 7) + (((lane >> 3) & 1) << 3)) * RPITCH
                            + (uint32_t)((lane >> 4) << 4);

    // staging: thread owns float4-column cc of rows rbase+8j
    const int rbase = tid >> 4;   // 0..7
    const int cc    = tid & 15;

    // ---- stage Q (fp32 -> fp16, once) ----
    #pragma unroll
    for (int j = 0; j < 8; j++) {
        int row = rbase + 8 * j;
        float4 f = *(const float4*)(qb + (size_t)(m0 + row) * Dh + cc * 4);
        *(uint2*)(smc + SM_Q + row * RPITCH + cc * 8) =
            make_uint2(ph2(f.x, f.y), ph2(f.z, f.w));
    }
    // ---- stage K/V tile 0 ----
    #pragma unroll
    for (int j = 0; j < 8; j++) {
        int row = rbase + 8 * j;
        float4 fk = *(const float4*)(kb + (size_t)row * Dh + cc * 4);
        float4 fv = *(const float4*)(vb + (size_t)row * Dh + cc * 4);
        *(uint2*)(smc + SM_K0 + row * RPITCH + cc * 8) =
            make_uint2(ph2(fk.x, fk.y), ph2(fk.z, fk.w));
        *(uint2*)(smc + SM_V0 + row * RPITCH + cc * 8) =
            make_uint2(ph2(fv.x, fv.y), ph2(fv.z, fv.w));
    }
    __syncthreads();

    float o[8][4];
    #pragma unroll
    for (int d = 0; d < 8; d++)
        #pragma unroll
        for (int r = 0; r < 4; r++) o[d][r] = 0.f;
    float rs0 = 0.f, rs1 = 0.f;

    for (int tt = 0; tt < NTILES; tt++) {
        const uint32_t kbase = sb + ((tt & 1) ? SM_K1 : SM_K0);
        const uint32_t vbase = sb + ((tt & 1) ? SM_V1 : SM_V0);
        char* kd = smc + ((tt & 1) ? SM_K0 : SM_K1);
        char* vd = smc + ((tt & 1) ? SM_V0 : SM_V1);
        const bool pf = (tt < NTILES - 1);
        const size_t nb = (size_t)(tt + 1) * BN;

        // ---- prefetch next K, convert to fp16 at load (16 regs) ----
        uint2 kf[8];
        if (pf) {
            #pragma unroll
            for (int j = 0; j < 8; j++) {
                float4 f = *(const float4*)(kb + (nb + rbase + 8 * j) * Dh + cc * 4);
                kf[j] = make_uint2(ph2(f.x, f.y), ph2(f.z, f.w));
            }
        }

        // ---- S = Q K^T : warp's 16 rows x all 64 keys ----
        float c[8][4];
        #pragma unroll
        for (int nf = 0; nf < 8; nf++)
            #pragma unroll
            for (int r = 0; r < 4; r++) c[nf][r] = 0.f;

        #pragma unroll
        for (int ks = 0; ks < 4; ks++) {
            uint32_t a[4];
            ldm_x4(a, qaddr + ks * 32);
            #pragma unroll
            for (int p = 0; p < 4; p++) {
                uint32_t b[4];
                ldm_x4(b, kbase + p * (16 * RPITCH) + ks * 32 + krow_off);
                mma16(c[2 * p],     a, b[0], b[1]);
                mma16(c[2 * p + 1], a, b[2], b[3]);
            }
        }

        // ---- poly + relu + rowsum (pre-rounded fp32) + repack to A-frags ----
        uint32_t ap[4][4];
        #pragma unroll
        for (int nf = 0; nf < 8; nf++) {
            float p0 = fmaxf(fmaf(fmaf(a2c, c[nf][0], b1c), c[nf][0], g0c), 0.f);
            float p1 = fmaxf(fmaf(fmaf(a2c, c[nf][1], b1c), c[nf][1], g0c), 0.f);
            float p2 = fmaxf(fmaf(fmaf(a2c, c[nf][2], b1c), c[nf][2], g0c), 0.f);
            float p3 = fmaxf(fmaf(fmaf(a2c, c[nf][3], b1c), c[nf][3], g0c), 0.f);
            rs0 += p0 + p1;
            rs1 += p2 + p3;
            ap[nf >> 1][(nf & 1) * 2 + 0] = ph2(p0, p1);
            ap[nf >> 1][(nf & 1) * 2 + 1] = ph2(p2, p3);
        }

        // ---- store prefetched K (kf dies), then prefetch next V (16 regs) ----
        uint2 vf[8];
        if (pf) {
            #pragma unroll
            for (int j = 0; j < 8; j++)
                *(uint2*)(kd + (rbase + 8 * j) * RPITCH + cc * 8) = kf[j];
            #pragma unroll
            for (int j = 0; j < 8; j++) {
                float4 f = *(const float4*)(vb + (nb + rbase + 8 * j) * Dh + cc * 4);
                vf[j] = make_uint2(ph2(f.x, f.y), ph2(f.z, f.w));
            }
        }

        // ---- O += attn @ V ----
        #pragma unroll
        for (int ks2 = 0; ks2 < 4; ks2++) {
            #pragma unroll
            for (int p = 0; p < 4; p++) {
                uint32_t b[4];
                ldm_x4t(b, vbase + ks2 * (16 * RPITCH) + p * 32 + vrow_off);
                mma16(o[2 * p],     ap[ks2], b[0], b[1]);
                mma16(o[2 * p + 1], ap[ks2], b[2], b[3]);
            }
        }

        // ---- store prefetched V, barrier before buffer swap ----
        if (pf) {
            #pragma unroll
            for (int j = 0; j < 8; j++)
                *(uint2*)(vd + (rbase + 8 * j) * RPITCH + cc * 8) = vf[j];
            __syncthreads();
        }
    }

    // ---- rowsum closes within warp (4 t-lanes) ----
    rs0 += __shfl_xor_sync(0xFFFFFFFFu, rs0, 1);
    rs0 += __shfl_xor_sync(0xFFFFFFFFu, rs0, 2);
    rs1 += __shfl_xor_sync(0xFFFFFFFFu, rs1, 1);
    rs1 += __shfl_xor_sync(0xFFFFFFFFu, rs1, 2);
    const float inv0 = 1.f / (rs0 + EPS);
    const float inv1 = 1.f / (rs1 + EPS);

    // ---- normalize + store ----
    const int row0 = m0 + w * 16 + g;
    #pragma unroll
    for (int d = 0; d < 8; d++) {
        float2 lo = {o[d][0] * inv0, o[d][1] * inv0};
        float2 hi = {o[d][2] * inv1, o[d][3] * inv1};
        *(float2*)(ob + (size_t)row0 * Dh + d * 8 + 2 * t)       = lo;
        *(float2*)(ob + (size_t)(row0 + 8) * Dh + d * 8 + 2 * t) = hi;
    }
}

extern "C" void kernel_launch(void* const* d_in, const int* in_sizes, int n_in,
                              void* d_out, int out_size)
{
    const float* q     = (const float*)d_in[0];
    const float* k     = (const float*)d_in[1];
    const float* v     = (const float*)d_in[2];
    const float* alpha = (const float*)d_in[3];
    const float* beta  = (const float*)d_in[4];
    const float* gamma = (const float*)d_in[5];
    float* out = (float*)d_out;

    cudaFuncSetAttribute(l2q_h7_kernel,
                         cudaFuncAttributeMaxDynamicSharedMemorySize, SMEM_BYTES);

    dim3 grid(Nq / BM, Bsz * H);
    l2q_h7_kernel<<<grid, NT, SMEM_BYTES>>>(q, k, v, alpha, beta, gamma, out);
}

// round 13
// speedup vs baseline: 1.0696x; 1.0696x over previous
#include <cuda_runtime.h>
#include <cuda_fp16.h>
#include <stdint.h>

#define Bsz 8
#define H   12
#define Nq  1024
#define Dh  64
#define SCALE 0.125f
#define EPS 1e-6f

#define BM 128
#define BN 64
#define NT 256
#define NTILES (Nq / BN)   // 16

// 128-byte rows, XOR-swizzled (SW128 pattern): off ^= (row&7)<<4
#define SWZ(row, off) ((uint32_t)(off) ^ (((uint32_t)(row) & 7u) << 4))

// smem byte offsets (rows of exactly 128 B)
#define SM_Q  0          // 128 rows -> 16384 B
#define SM_K0 16384      // 64 rows  -> 8192 B
#define SM_K1 24576
#define SM_V0 32768
#define SM_V1 40960
#define SMEM_BYTES 49152

__device__ __forceinline__ uint32_t s2u(const void* p) {
    uint32_t a;
    asm("{ .reg .u64 t; cvta.to.shared.u64 t, %1; cvt.u32.u64 %0, t; }" : "=r"(a) : "l"(p));
    return a;
}
__device__ __forceinline__ uint32_t ph2(float lo, float hi) {
    __half2 h = __floats2half2_rn(lo, hi);
    return *(uint32_t*)&h;
}
__device__ __forceinline__ void ldm_x4(uint32_t r[4], uint32_t addr) {
    asm volatile("ldmatrix.sync.aligned.m8n8.x4.shared.b16 {%0,%1,%2,%3}, [%4];"
                 : "=r"(r[0]), "=r"(r[1]), "=r"(r[2]), "=r"(r[3]) : "r"(addr));
}
__device__ __forceinline__ void ldm_x4t(uint32_t r[4], uint32_t addr) {
    asm volatile("ldmatrix.sync.aligned.m8n8.x4.trans.shared.b16 {%0,%1,%2,%3}, [%4];"
                 : "=r"(r[0]), "=r"(r[1]), "=r"(r[2]), "=r"(r[3]) : "r"(addr));
}
__device__ __forceinline__ void mma16(float c[4], const uint32_t a[4],
                                      uint32_t b0, uint32_t b1) {
    asm volatile(
        "mma.sync.aligned.m16n8k16.row.col.f32.f16.f16.f32 "
        "{%0,%1,%2,%3},{%4,%5,%6,%7},{%8,%9},{%0,%1,%2,%3};\n"
        : "+f"(c[0]), "+f"(c[1]), "+f"(c[2]), "+f"(c[3])
        : "r"(a[0]), "r"(a[1]), "r"(a[2]), "r"(a[3]), "r"(b0), "r"(b1));
}

__global__ __launch_bounds__(NT, 2) void l2q_h8_kernel(
    const float* __restrict__ q, const float* __restrict__ k,
    const float* __restrict__ v, const float* __restrict__ alpha,
    const float* __restrict__ beta, const float* __restrict__ gamma,
    float* __restrict__ out)
{
    extern __shared__ char smc[];
    const uint32_t sb = s2u(smc);

    const int tid  = threadIdx.x;
    const int w    = tid >> 5;    // warp 0..7 -> rows w*16..w*16+15
    const int lane = tid & 31;
    const int g    = lane >> 2;
    const int t    = lane & 3;

    const int bh = blockIdx.y;
    const int h  = bh % H;
    const int m0 = blockIdx.x * BM;

    const float* qb = q + (size_t)bh * Nq * Dh;
    const float* kb = k + (size_t)bh * Nq * Dh;
    const float* vb = v + (size_t)bh * Nq * Dh;
    float*       ob = out + (size_t)bh * Nq * Dh;

    const float a2c = alpha[h] * SCALE * SCALE;
    const float b1c = beta[h] * SCALE;
    const float g0c = gamma[h];

    // ---- ldmatrix lane geometry (same fragment maps as rounds 4-12, swizzled) ----
    // A (Q, non-trans): row = w*16 + (lane&15); 16B chunk col = (lane>>4) (+2*ks)
    const int qrow  = w * 16 + (lane & 15);
    const uint32_t qbase = sb + SM_Q + (uint32_t)qrow * 128;
    const uint32_t qswz  = ((uint32_t)qrow & 7u) << 4;
    const uint32_t qhi   = (uint32_t)(lane >> 4) << 4;
    // B (K, non-trans): local row = (lane&7) + ((lane>>4)<<3) within 16-row group p
    const int krow  = (lane & 7) + ((lane >> 4) << 3);
    const uint32_t kswz = ((uint32_t)krow & 7u) << 4;
    const uint32_t kb8  = (((uint32_t)lane >> 3) & 1u) << 4;
    // B (V, trans): local row = (lane&7) + (((lane>>3)&1)<<3) within 16-row group ks2
    const int vrow  = (lane & 7) + (((lane >> 3) & 1) << 3);
    const uint32_t vswz = ((uint32_t)vrow & 7u) << 4;
    const uint32_t vhi  = (uint32_t)(lane >> 4) << 4;

    // staging: thread owns 16B-chunk cc of rows rbase+16j
    const int rbase = tid >> 4;   // 0..15
    const int cc    = tid & 15;   // but only 8 chunks/row -> cc&7, cc>>3 selects half rows? No:
    // rows have 8 chunks (128B). Use: thread (tid) -> row = tid>>3 (0..31), chunk = tid&7
    const int srow = tid >> 3;    // 0..31
    const int sch  = tid & 7;     // 0..7

    // ---- stage Q (fp32 -> fp16, once): 128 rows x 8 chunks / 256 thr = 4 iters ----
    #pragma unroll
    for (int j = 0; j < 4; j++) {
        int row = srow + 32 * j;
        float4 f = *(const float4*)(qb + (size_t)(m0 + row) * Dh + sch * 8);
        float4 f2 = *(const float4*)(qb + (size_t)(m0 + row) * Dh + sch * 8 + 4);
        *(uint4*)(smc + SM_Q + row * 128 + SWZ(row, sch * 16)) =
            make_uint4(ph2(f.x, f.y), ph2(f.z, f.w), ph2(f2.x, f2.y), ph2(f2.z, f2.w));
    }
    // ---- stage K/V tile 0 : 64 rows x 8 chunks / 256 thr = 2 iters ----
    #pragma unroll
    for (int j = 0; j < 2; j++) {
        int row = srow + 32 * j;
        float4 a = *(const float4*)(kb + (size_t)row * Dh + sch * 8);
        float4 b = *(const float4*)(kb + (size_t)row * Dh + sch * 8 + 4);
        *(uint4*)(smc + SM_K0 + row * 128 + SWZ(row, sch * 16)) =
            make_uint4(ph2(a.x, a.y), ph2(a.z, a.w), ph2(b.x, b.y), ph2(b.z, b.w));
        float4 c = *(const float4*)(vb + (size_t)row * Dh + sch * 8);
        float4 d = *(const float4*)(vb + (size_t)row * Dh + sch * 8 + 4);
        *(uint4*)(smc + SM_V0 + row * 128 + SWZ(row, sch * 16)) =
            make_uint4(ph2(c.x, c.y), ph2(c.z, c.w), ph2(d.x, d.y), ph2(d.z, d.w));
    }
    __syncthreads();

    float o[8][4];
    #pragma unroll
    for (int d = 0; d < 8; d++)
        #pragma unroll
        for (int r = 0; r < 4; r++) o[d][r] = 0.f;
    float rs0 = 0.f, rs1 = 0.f;

    for (int tt = 0; tt < NTILES; tt++) {
        const uint32_t kbase = sb + ((tt & 1) ? SM_K1 : SM_K0);
        const uint32_t vbase = sb + ((tt & 1) ? SM_V1 : SM_V0);
        char* kd = smc + ((tt & 1) ? SM_K0 : SM_K1);
        char* vd = smc + ((tt & 1) ? SM_V0 : SM_V1);
        const bool pf = (tt < NTILES - 1);
        const size_t nb = (size_t)(tt + 1) * BN;

        // ---- prefetch next K, convert to fp16 at load (16 regs) ----
        uint4 kf[2];
        if (pf) {
            #pragma unroll
            for (int j = 0; j < 2; j++) {
                int row = srow + 32 * j;
                float4 a = *(const float4*)(kb + (nb + row) * Dh + sch * 8);
                float4 b = *(const float4*)(kb + (nb + row) * Dh + sch * 8 + 4);
                kf[j] = make_uint4(ph2(a.x, a.y), ph2(a.z, a.w),
                                   ph2(b.x, b.y), ph2(b.z, b.w));
            }
        }

        // ---- S = Q K^T : warp's 16 rows x all 64 keys ----
        float c[8][4];
        #pragma unroll
        for (int nf = 0; nf < 8; nf++)
            #pragma unroll
            for (int r = 0; r < 4; r++) c[nf][r] = 0.f;

        #pragma unroll
        for (int ks = 0; ks < 4; ks++) {
            uint32_t a[4];
            ldm_x4(a, qbase + ((ks * 32 + qhi) ^ qswz));
            #pragma unroll
            for (int p = 0; p < 4; p++) {
                uint32_t b[4];
                ldm_x4(b, kbase + (uint32_t)(p * 16 + krow) * 128
                              + ((ks * 32 + kb8) ^ kswz));
                mma16(c[2 * p],     a, b[0], b[1]);
                mma16(c[2 * p + 1], a, b[2], b[3]);
            }
        }

        // ---- poly + relu + rowsum (pre-rounded fp32) + repack to A-frags ----
        uint32_t ap[4][4];
        #pragma unroll
        for (int nf = 0; nf < 8; nf++) {
            float p0 = fmaxf(fmaf(fmaf(a2c, c[nf][0], b1c), c[nf][0], g0c), 0.f);
            float p1 = fmaxf(fmaf(fmaf(a2c, c[nf][1], b1c), c[nf][1], g0c), 0.f);
            float p2 = fmaxf(fmaf(fmaf(a2c, c[nf][2], b1c), c[nf][2], g0c), 0.f);
            float p3 = fmaxf(fmaf(fmaf(a2c, c[nf][3], b1c), c[nf][3], g0c), 0.f);
            rs0 += p0 + p1;
            rs1 += p2 + p3;
            ap[nf >> 1][(nf & 1) * 2 + 0] = ph2(p0, p1);
            ap[nf >> 1][(nf & 1) * 2 + 1] = ph2(p2, p3);
        }

        // ---- store prefetched K (kf dies), then prefetch next V (16 regs) ----
        uint4 vf[2];
        if (pf) {
            #pragma unroll
            for (int j = 0; j < 2; j++) {
                int row = srow + 32 * j;
                *(uint4*)(kd + row * 128 + SWZ(row, sch * 16)) = kf[j];
            }
            #pragma unroll
            for (int j = 0; j < 2; j++) {
                int row = srow + 32 * j;
                float4 a = *(const float4*)(vb + (nb + row) * Dh + sch * 8);
                float4 b = *(const float4*)(vb + (nb + row) * Dh + sch * 8 + 4);
                vf[j] = make_uint4(ph2(a.x, a.y), ph2(a.z, a.w),
                                   ph2(b.x, b.y), ph2(b.z, b.w));
            }
        }

        // ---- O += attn @ V ----
        #pragma unroll
        for (int ks2 = 0; ks2 < 4; ks2++) {
            #pragma unroll
            for (int p = 0; p < 4; p++) {
                uint32_t b[4];
                ldm_x4t(b, vbase + (uint32_t)(ks2 * 16 + vrow) * 128
                               + ((p * 32 + vhi) ^ vswz));
                mma16(o[2 * p],     ap[ks2], b[0], b[1]);
                mma16(o[2 * p + 1], ap[ks2], b[2], b[3]);
            }
        }

        // ---- store prefetched V, barrier before buffer swap ----
        if (pf) {
            #pragma unroll
            for (int j = 0; j < 2; j++) {
                int row = srow + 32 * j;
                *(uint4*)(vd + row * 128 + SWZ(row, sch * 16)) = vf[j];
            }
            __syncthreads();
        }
    }

    // ---- rowsum closes within warp (4 t-lanes) ----
    rs0 += __shfl_xor_sync(0xFFFFFFFFu, rs0, 1);
    rs0 += __shfl_xor_sync(0xFFFFFFFFu, rs0, 2);
    rs1 += __shfl_xor_sync(0xFFFFFFFFu, rs1, 1);
    rs1 += __shfl_xor_sync(0xFFFFFFFFu, rs1, 2);
    const float inv0 = 1.f / (rs0 + EPS);
    const float inv1 = 1.f / (rs1 + EPS);

    // ---- normalize + store ----
    const int row0 = m0 + w * 16 + g;
    #pragma unroll
    for (int d = 0; d < 8; d++) {
        float2 lo = {o[d][0] * inv0, o[d][1] * inv0};
        float2 hi = {o[d][2] * inv1, o[d][3] * inv1};
        *(float2*)(ob + (size_t)row0 * Dh + d * 8 + 2 * t)       = lo;
        *(float2*)(ob + (size_t)(row0 + 8) * Dh + d * 8 + 2 * t) = hi;
    }
}

extern "C" void kernel_launch(void* const* d_in, const int* in_sizes, int n_in,
                              void* d_out, int out_size)
{
    const float* q     = (const float*)d_in[0];
    const float* k     = (const float*)d_in[1];
    const float* v     = (const float*)d_in[2];
    const float* alpha = (const float*)d_in[3];
    const float* beta  = (const float*)d_in[4];
    const float* gamma = (const float*)d_in[5];
    float* out = (float*)d_out;

    cudaFuncSetAttribute(l2q_h8_kernel,
                         cudaFuncAttributeMaxDynamicSharedMemorySize, SMEM_BYTES);

    dim3 grid(Nq / BM, Bsz * H);
    l2q_h8_kernel<<<grid, NT, SMEM_BYTES>>>(q, k, v, alpha, beta, gamma, out);
}

// round 14
// speedup vs baseline: 1.1336x; 1.0599x over previous
#include <cuda_runtime.h>
#include <cuda_fp16.h>
#include <stdint.h>

#define Bsz 8
#define H   12
#define Nq  1024
#define Dh  64
#define SCALE 0.125f
#define EPS 1e-6f

#define BM 128
#define BN 64
#define NT 256
#define NTILES (Nq / BN)   // 16
#define RPITCH 144          // bytes per smem row (72 halves: 64 data + 8 pad)

// smem byte offsets
#define SM_Q  0                       // 128 rows -> 18432 B
#define SM_K0 18432                   // 64 rows  -> 9216 B
#define SM_K1 (18432 + 9216)
#define SM_V0 36864
#define SM_V1 (36864 + 9216)
#define SMEM_BYTES 55296

__device__ __forceinline__ uint32_t s2u(const void* p) {
    uint32_t a;
    asm("{ .reg .u64 t; cvta.to.shared.u64 t, %1; cvt.u32.u64 %0, t; }" : "=r"(a) : "l"(p));
    return a;
}
__device__ __forceinline__ uint32_t ph2(float lo, float hi) {
    __half2 h = __floats2half2_rn(lo, hi);
    return *(uint32_t*)&h;
}
__device__ __forceinline__ void ldm_x4(uint32_t r[4], uint32_t addr) {
    asm volatile("ldmatrix.sync.aligned.m8n8.x4.shared.b16 {%0,%1,%2,%3}, [%4];"
                 : "=r"(r[0]), "=r"(r[1]), "=r"(r[2]), "=r"(r[3]) : "r"(addr));
}
__device__ __forceinline__ void ldm_x4t(uint32_t r[4], uint32_t addr) {
    asm volatile("ldmatrix.sync.aligned.m8n8.x4.trans.shared.b16 {%0,%1,%2,%3}, [%4];"
                 : "=r"(r[0]), "=r"(r[1]), "=r"(r[2]), "=r"(r[3]) : "r"(addr));
}
__device__ __forceinline__ void mma16(float c[4], const uint32_t a[4],
                                      uint32_t b0, uint32_t b1) {
    asm volatile(
        "mma.sync.aligned.m16n8k16.row.col.f32.f16.f16.f32 "
        "{%0,%1,%2,%3},{%4,%5,%6,%7},{%8,%9},{%0,%1,%2,%3};\n"
        : "+f"(c[0]), "+f"(c[1]), "+f"(c[2]), "+f"(c[3])
        : "r"(a[0]), "r"(a[1]), "r"(a[2]), "r"(a[3]), "r"(b0), "r"(b1));
}

__global__ __launch_bounds__(NT, 2) void l2q_h9_kernel(
    const float* __restrict__ q, const float* __restrict__ k,
    const float* __restrict__ v, const float* __restrict__ alpha,
    const float* __restrict__ beta, const float* __restrict__ gamma,
    float* __restrict__ out)
{
    extern __shared__ char smc[];
    const uint32_t sb = s2u(smc);

    const int tid  = threadIdx.x;
    const int w    = tid >> 5;    // warp 0..7 -> rows w*16..w*16+15
    const int lane = tid & 31;
    const int g    = lane >> 2;
    const int t    = lane & 3;

    const int bh = blockIdx.y;
    const int h  = bh % H;
    const int m0 = blockIdx.x * BM;

    const float* qb = q + (size_t)bh * Nq * Dh;
    const float* kb = k + (size_t)bh * Nq * Dh;
    const float* vb = v + (size_t)bh * Nq * Dh;
    float*       ob = out + (size_t)bh * Nq * Dh;

    const float a2c = alpha[h] * SCALE * SCALE;
    const float b1c = beta[h] * SCALE;
    const float g0c = gamma[h];

    // ldmatrix lane-address offsets (r4-verified layouts)
    const uint32_t qaddr = sb + SM_Q + (uint32_t)(w * 16 + (lane & 15)) * RPITCH
                         + (uint32_t)((lane >> 4) << 4);
    const uint32_t krow_off = (uint32_t)((lane & 7) + ((lane >> 4) << 3)) * RPITCH
                            + (uint32_t)(((lane >> 3) & 1) << 4);
    const uint32_t vrow_off = (uint32_t)((lane & 7) + (((lane >> 3) & 1) << 3)) * RPITCH
                            + (uint32_t)((lane >> 4) << 4);

    // staging: thread owns float4-column cc of rows rbase+16j
    const int rbase = tid >> 4;   // 0..15
    const int cc    = tid & 15;

    // ---- stage Q (fp32 -> fp16, once) ----
    #pragma unroll
    for (int j = 0; j < 8; j++) {
        int row = rbase + 16 * j;
        float4 f = *(const float4*)(qb + (size_t)(m0 + row) * Dh + cc * 4);
        *(uint2*)(smc + SM_Q + row * RPITCH + cc * 8) =
            make_uint2(ph2(f.x, f.y), ph2(f.z, f.w));
    }
    // ---- stage K/V tile 0 ----
    #pragma unroll
    for (int j = 0; j < 4; j++) {
        int row = rbase + 16 * j;
        float4 fk = *(const float4*)(kb + (size_t)row * Dh + cc * 4);
        float4 fv = *(const float4*)(vb + (size_t)row * Dh + cc * 4);
        *(uint2*)(smc + SM_K0 + row * RPITCH + cc * 8) =
            make_uint2(ph2(fk.x, fk.y), ph2(fk.z, fk.w));
        *(uint2*)(smc + SM_V0 + row * RPITCH + cc * 8) =
            make_uint2(ph2(fv.x, fv.y), ph2(fv.z, fv.w));
    }
    __syncthreads();

    float o[8][4];
    #pragma unroll
    for (int d = 0; d < 8; d++)
        #pragma unroll
        for (int r = 0; r < 4; r++) o[d][r] = 0.f;
    float rs0 = 0.f, rs1 = 0.f;

    for (int tt = 0; tt < NTILES; tt++) {
        const uint32_t kbase = sb + ((tt & 1) ? SM_K1 : SM_K0);
        const uint32_t vbase = sb + ((tt & 1) ? SM_V1 : SM_V0);
        char* kd = smc + ((tt & 1) ? SM_K0 : SM_K1);
        char* vd = smc + ((tt & 1) ? SM_V0 : SM_V1);
        const bool pf = (tt < NTILES - 1);
        const size_t nb = (size_t)(tt + 1) * BN;

        // ---- prefetch next K, convert at load (8 regs) ----
        uint2 kf[4];
        if (pf) {
            #pragma unroll
            for (int j = 0; j < 4; j++) {
                float4 f = *(const float4*)(kb + (nb + rbase + 16 * j) * Dh + cc * 4);
                kf[j] = make_uint2(ph2(f.x, f.y), ph2(f.z, f.w));
            }
        }

        // ---- S = Q K^T : 16 pipelined steps (ks = i>>2, p = i&3) ----
        float c[8][4];
        #pragma unroll
        for (int nf = 0; nf < 8; nf++)
            #pragma unroll
            for (int r = 0; r < 4; r++) c[nf][r] = 0.f;

        {
            uint32_t a[2][4], b[2][4];
            ldm_x4(a[0], qaddr);
            ldm_x4(b[0], kbase + krow_off);
            #pragma unroll
            for (int i = 0; i < 16; i++) {
                const int ks = i >> 2, p = i & 3;
                // prefetch next B fragment one step ahead
                if (i < 15) {
                    const int i1 = i + 1;
                    ldm_x4(b[i1 & 1], kbase + (i1 & 3) * (16 * RPITCH)
                                            + (i1 >> 2) * 32 + krow_off);
                }
                // prefetch next A fragment two steps before its first use
                if (p == 2 && ks < 3)
                    ldm_x4(a[(ks + 1) & 1], qaddr + (ks + 1) * 32);
                mma16(c[2 * p],     a[ks & 1], b[i & 1][0], b[i & 1][1]);
                mma16(c[2 * p + 1], a[ks & 1], b[i & 1][2], b[i & 1][3]);
            }
        }

        // ---- poly + relu + rowsum (pre-rounded fp32) + repack to A-frags ----
        uint32_t ap[4][4];
        #pragma unroll
        for (int nf = 0; nf < 8; nf++) {
            float p0 = fmaxf(fmaf(fmaf(a2c, c[nf][0], b1c), c[nf][0], g0c), 0.f);
            float p1 = fmaxf(fmaf(fmaf(a2c, c[nf][1], b1c), c[nf][1], g0c), 0.f);
            float p2 = fmaxf(fmaf(fmaf(a2c, c[nf][2], b1c), c[nf][2], g0c), 0.f);
            float p3 = fmaxf(fmaf(fmaf(a2c, c[nf][3], b1c), c[nf][3], g0c), 0.f);
            rs0 += p0 + p1;
            rs1 += p2 + p3;
            ap[nf >> 1][(nf & 1) * 2 + 0] = ph2(p0, p1);
            ap[nf >> 1][(nf & 1) * 2 + 1] = ph2(p2, p3);
        }

        // ---- store prefetched K (kf dies), then prefetch next V (8 regs) ----
        uint2 vf[4];
        if (pf) {
            #pragma unroll
            for (int j = 0; j < 4; j++)
                *(uint2*)(kd + (rbase + 16 * j) * RPITCH + cc * 8) = kf[j];
            #pragma unroll
            for (int j = 0; j < 4; j++) {
                float4 f = *(const float4*)(vb + (nb + rbase + 16 * j) * Dh + cc * 4);
                vf[j] = make_uint2(ph2(f.x, f.y), ph2(f.z, f.w));
            }
        }

        // ---- O += attn @ V : 16 pipelined steps (ks2 = i>>2, p = i&3) ----
        {
            uint32_t b[2][4];
            ldm_x4t(b[0], vbase + vrow_off);
            #pragma unroll
            for (int i = 0; i < 16; i++) {
                if (i < 15) {
                    const int i1 = i + 1;
                    ldm_x4t(b[i1 & 1], vbase + (i1 >> 2) * (16 * RPITCH)
                                             + (i1 & 3) * 32 + vrow_off);
                }
                const int p = i & 3;
                mma16(o[2 * p],     ap[i >> 2], b[i & 1][0], b[i & 1][1]);
                mma16(o[2 * p + 1], ap[i >> 2], b[i & 1][2], b[i & 1][3]);
            }
        }

        // ---- store prefetched V, barrier before buffer swap ----
        if (pf) {
            #pragma unroll
            for (int j = 0; j < 4; j++)
                *(uint2*)(vd + (rbase + 16 * j) * RPITCH + cc * 8) = vf[j];
            __syncthreads();
        }
    }

    // ---- rowsum closes within warp (4 t-lanes) ----
    rs0 += __shfl_xor_sync(0xFFFFFFFFu, rs0, 1);
    rs0 += __shfl_xor_sync(0xFFFFFFFFu, rs0, 2);
    rs1 += __shfl_xor_sync(0xFFFFFFFFu, rs1, 1);
    rs1 += __shfl_xor_sync(0xFFFFFFFFu, rs1, 2);
    const float inv0 = 1.f / (rs0 + EPS);
    const float inv1 = 1.f / (rs1 + EPS);

    // ---- normalize + store ----
    const int row0 = m0 + w * 16 + g;
    #pragma unroll
    for (int d = 0; d < 8; d++) {
        float2 lo = {o[d][0] * inv0, o[d][1] * inv0};
        float2 hi = {o[d][2] * inv1, o[d][3] * inv1};
        *(float2*)(ob + (size_t)row0 * Dh + d * 8 + 2 * t)       = lo;
        *(float2*)(ob + (size_t)(row0 + 8) * Dh + d * 8 + 2 * t) = hi;
    }
}

extern "C" void kernel_launch(void* const* d_in, const int* in_sizes, int n_in,
                              void* d_out, int out_size)
{
    const float* q     = (const float*)d_in[0];
    const float* k     = (const float*)d_in[1];
    const float* v     = (const float*)d_in[2];
    const float* alpha = (const float*)d_in[3];
    const float* beta  = (const float*)d_in[4];
    const float* gamma = (const float*)d_in[5];
    float* out = (float*)d_out;

    cudaFuncSetAttribute(l2q_h9_kernel,
                         cudaFuncAttributeMaxDynamicSharedMemorySize, SMEM_BYTES);

    dim3 grid(Nq / BM, Bsz * H);
    l2q_h9_kernel<<<grid, NT, SMEM_BYTES>>>(q, k, v, alpha, beta, gamma, out);
}